// round 11
// baseline (speedup 1.0000x reference)
#include <cuda_runtime.h>
#include <cstdint>

// ---------------------------------------------------------------------------
// Block-diagonal linear (256x0e+256x1o+256x2e): 3 GEMMs over rows (z,i):
//   A'[z*D+i][u] = feat[z, XOFF + u*D + i];  C = A' * W_b / 16.
// R11 = R10 (cp.async native A + pre-fragmented tf32 B via prepass, 3-stage
// ring, 1 barrier/chunk, 2 CTAs/SM) + D>1 epilogue repack: C staged to smem
// [row][n] then written back as contiguous per-z spans with STG.128
// (kills scatter-store wavefronts + DRAM partial-sector amplification).
// mma.sync m16n8k8 tf32 (PTX targets compute_103; tcgen05 unavailable).
// ---------------------------------------------------------------------------
#define HX_BZ   50000
#define HX_FEAT 2304

static constexpr int NTH = 256;   // 8 warps: wm = wid>>1 (4x32 rows), wn = wid&1

// pre-fragmented weights: [b*2+nh][ch][1024 uint4]  (3*2*8*1024 = 49152)
__device__ uint4 g_wfrag[49152];

// ---------------------------------------------------------------------------
__device__ __forceinline__ uint32_t f2tf(float x) {
    uint32_t r;
    asm("cvt.rna.tf32.f32 %0, %1;" : "=r"(r) : "f"(x));
    return r;
}

__device__ __forceinline__ void mma8(float* c, const uint32_t* a,
                                     uint32_t b0, uint32_t b1) {
    asm volatile(
        "mma.sync.aligned.m16n8k8.row.col.f32.tf32.tf32.f32 "
        "{%0,%1,%2,%3}, {%4,%5,%6,%7}, {%8,%9}, {%0,%1,%2,%3};"
        : "+f"(c[0]), "+f"(c[1]), "+f"(c[2]), "+f"(c[3])
        : "r"(a[0]), "r"(a[1]), "r"(a[2]), "r"(a[3]), "r"(b0), "r"(b1));
}

#define CP_A16(dst, src, sz)                                               \
    asm volatile("cp.async.cg.shared.global [%0], [%1], 16, %2;"           \
                 :: "r"(dst), "l"(src), "r"(sz) : "memory")
#define CP_COMMIT() asm volatile("cp.async.commit_group;" ::: "memory")
#define CP_WAIT(n)  asm volatile("cp.async.wait_group %0;" :: "n"(n) : "memory")

__device__ __forceinline__ uint32_t smem_u32(const void* p) {
    uint32_t a;
    asm("{ .reg .u64 t; cvta.to.shared.u64 t, %1; cvt.u32.u64 %0, t; }"
        : "=r"(a) : "l"(p));
    return a;
}

// ---------------------------------------------------------------------------
// Prepass: fragment-order + tf32-round all weights (once, ~3us).
__global__ void prep_w(const float* __restrict__ wt) {
    const int t = blockIdx.x * blockDim.x + threadIdx.x;
    if (t >= 49152) return;
    const int e  = t & 1023;
    const int ch = (t >> 10) & 7;
    const int bn = t >> 13;              // b*2 + nh
    const int b  = bn >> 1, nh = bn & 1;
    const int woff = (b == 0) ? 0 : (b == 1) ? 65536 : 131072;
    const int l5 = e & 31, gg = l5 >> 2, tt = l5 & 3;
    const int blk = e >> 5, nfp = blk & 3, wnn = (blk >> 2) & 1, s = blk >> 3;
    const int k = 32 * ch + 8 * s + tt;
    const int n = 128 * nh + 64 * wnn + 16 * nfp + gg;
    const float* wp = wt + woff + k * 256 + n;
    uint4 q;
    q.x = f2tf(wp[0]);
    q.y = f2tf(wp[1024]);   // k+4
    q.z = f2tf(wp[8]);      // n+8
    q.w = f2tf(wp[1032]);
    g_wfrag[t] = q;
}

// ---------------------------------------------------------------------------
template<int D, int XOFF, int MTOT>
__global__ void __launch_bounds__(NTH, 2)
lin_k(const float* __restrict__ feat, float* __restrict__ out)
{
    constexpr int SD   = (D == 1) ? 36 : (D == 3) ? 104 : 168;
    constexpr int NZ   = (D == 1) ? 128 : (D == 3) ? 44 : 27;
    constexpr int F4Z  = 8 * D;
    constexpr int TOT4 = NZ * F4Z;
    constexpr int PA   = (TOT4 + NTH - 1) / NTH;       // 4 / 5 / 5
    constexpr int ABUF = NZ * SD * 4;                  // bytes per A stage
    constexpr int BOFF = 3 * ABUF;
    constexpr int BBUF = 16384;

    extern __shared__ char smem[];
    const uint32_t smb = smem_u32(smem);

    const int tid  = threadIdx.x;
    const int lane = tid & 31;
    const int wid  = tid >> 5;
    const int g    = lane >> 2;
    const int tg   = lane & 3;
    const int wm   = wid >> 1;
    const int wn   = wid & 1;

    const int bid  = blockIdx.x;
    const int tile = bid >> 1;
    const int nh   = bid & 1;
    const int m0   = tile * 128;
    const int z0   = m0 / D;

    const int bsel = ((D == 1) ? 0 : (D == 3) ? 2 : 4) + nh;
    const char* bbase = (const char*)(g_wfrag + bsel * 8192);

    // ---- A staging decode: PA float4 per thread ----
    const char* asrc[PA];
    uint32_t    adst[PA];
    uint32_t    aszr[PA];
    #pragma unroll
    for (int p = 0; p < PA; p++) {
        const int e  = tid + NTH * p;
        const int zr = e / F4Z;
        const int q  = e - zr * F4Z;
        const int z  = z0 + zr;
        const bool ok = (e < TOT4) && (z < HX_BZ);
        aszr[p] = ok ? 16u : 0u;
        asrc[p] = (const char*)(feat + (size_t)z * HX_FEAT + XOFF) + q * 16;
        adst[p] = (uint32_t)(zr * SD * 4 + q * 16);
        if (e >= TOT4) adst[p] = 0xFFFFFFFFu;
    }

    auto issue = [&](int ch, int st) {
        const uint32_t sa0 = smb + st * ABUF;
        const int aoff = ch * (32 * D) * 4;
        #pragma unroll
        for (int p = 0; p < PA; p++)
            if (adst[p] != 0xFFFFFFFFu)
                CP_A16(sa0 + adst[p], asrc[p] + aoff, aszr[p]);
        const uint32_t sb0 = smb + BOFF + st * BBUF + tid * 16;
        const char* bsrc = bbase + ch * BBUF + tid * 16;
        #pragma unroll
        for (int p = 0; p < 4; p++)
            CP_A16(sb0 + p * (NTH * 16), bsrc + p * (NTH * 16), 16u);
        CP_COMMIT();
    };

    // ---- fragment row decode for A (once per tile) ----
    int arow[2][2];
    #pragma unroll
    for (int mf = 0; mf < 2; mf++)
        #pragma unroll
        for (int hh = 0; hh < 2; hh++) {
            const int r  = wm * 32 + mf * 16 + hh * 8 + g;
            const int gr = m0 + r;
            const int z  = gr / D;
            const int i  = gr - z * D;
            arow[mf][hh] = (z - z0) * SD + i;
        }
    const int tgD = tg * D;

    // ---- accumulators ----
    float c[2][8][4];
    #pragma unroll
    for (int mf = 0; mf < 2; mf++)
        #pragma unroll
        for (int nf = 0; nf < 8; nf++)
            #pragma unroll
            for (int q = 0; q < 4; q++) c[mf][nf][q] = 0.0f;

    auto compute = [&](int st) {
        const float* Af = (const float*)(smem + st * ABUF);
        const uint4* Bs = (const uint4*)(smem + BOFF + st * BBUF);
        #pragma unroll
        for (int s = 0; s < 4; s++) {
            const int ks = 8 * s * D + tgD;
            uint32_t a[2][4];
            #pragma unroll
            for (int mf = 0; mf < 2; mf++) {
                a[mf][0] = f2tf(Af[arow[mf][0] + ks]);
                a[mf][1] = f2tf(Af[arow[mf][1] + ks]);
                a[mf][2] = f2tf(Af[arow[mf][0] + ks + 4 * D]);
                a[mf][3] = f2tf(Af[arow[mf][1] + ks + 4 * D]);
            }
            #pragma unroll
            for (int nfp = 0; nfp < 4; nfp++) {
                const uint4 b = Bs[((s * 2 + wn) * 4 + nfp) * 32 + lane];
                mma8(c[0][2 * nfp],     a[0], b.x, b.y);
                mma8(c[1][2 * nfp],     a[1], b.x, b.y);
                mma8(c[0][2 * nfp + 1], a[0], b.z, b.w);
                mma8(c[1][2 * nfp + 1], a[1], b.z, b.w);
            }
        }
    };

    // ---- pipeline: joint 3-stage ring, depth-2 prefetch, 1 barrier/chunk --
    issue(0, 0);
    issue(1, 1);
    CP_WAIT(1);
    __syncthreads();

    #pragma unroll 1
    for (int ch = 0; ch < 8; ch++) {
        compute(ch % 3);
        if (ch < 7) {
            if (ch + 2 < 8) {
                issue(ch + 2, (ch + 2) % 3);
                CP_WAIT(1);
            } else {
                CP_WAIT(0);
            }
            __syncthreads();
        }
    }

    // ---- epilogue ----
    const float S = 0.0625f;
    if (D == 1) {
        // direct, already coalesced (contiguous n within row z)
        #pragma unroll
        for (int mf = 0; mf < 2; mf++) {
            #pragma unroll
            for (int rr = 0; rr < 2; rr++) {
                const int z = m0 + wm * 32 + mf * 16 + rr * 8 + g;
                if (z < HX_BZ) {
                    float* op = out + (size_t)z * HX_FEAT + XOFF + nh * 128;
                    #pragma unroll
                    for (int nf = 0; nf < 8; nf++) {
                        const int n = wn * 64 + nf * 8 + 2 * tg;
                        float2 v;
                        v.x = c[mf][nf][rr * 2 + 0] * S;
                        v.y = c[mf][nf][rr * 2 + 1] * S;
                        *(float2*)(op + n) = v;
                    }
                }
            }
        }
    } else {
        // repack via smem: [row][n] stride 132, then contiguous per-z STG.128
        __syncthreads();                 // all warps done reading stage smem
        float* scr = (float*)smem;       // 128 * 132 * 4 = 67584 B (fits)
        #pragma unroll
        for (int mf = 0; mf < 2; mf++) {
            #pragma unroll
            for (int rr = 0; rr < 2; rr++) {
                const int row = wm * 32 + mf * 16 + rr * 8 + g;
                #pragma unroll
                for (int nf = 0; nf < 8; nf++) {
                    const int n = wn * 64 + nf * 8 + 2 * tg;
                    float2 v;
                    v.x = c[mf][nf][rr * 2 + 0] * S;
                    v.y = c[mf][nf][rr * 2 + 1] * S;
                    *(float2*)(scr + row * 132 + n) = v;
                }
            }
        }
        __syncthreads();
        constexpr int F4ZO = 32 * D;     // float4 per z in this nh slice
        constexpr int TOTO = NZ * F4ZO;
        const int ro2 = m0 - z0 * D;
        #pragma unroll 1
        for (int e = tid; e < TOTO; e += NTH) {
            const int zr = e / F4ZO;
            const int t4 = e - zr * F4ZO;
            const int z  = z0 + zr;
            if (z >= HX_BZ) break;       // zr non-decreasing in e
            const int t0 = t4 * 4;
            float f[4]; bool ok[4]; bool all = true;
            #pragma unroll
            for (int j = 0; j < 4; j++) {
                const int t = t0 + j;
                const int n = t / D;
                const int i = t - n * D;
                const int row = zr * D + i - ro2;
                ok[j] = ((unsigned)row < 128u);
                all &= ok[j];
                f[j] = ok[j] ? scr[row * 132 + n] : 0.f;
            }
            float* op = out + (size_t)z * HX_FEAT + XOFF + nh * (128 * D) + t0;
            if (all) {
                *(float4*)op = make_float4(f[0], f[1], f[2], f[3]);
            } else {
                #pragma unroll
                for (int j = 0; j < 4; j++) if (ok[j]) op[j] = f[j];
            }
        }
    }
}

// ---------------------------------------------------------------------------
extern "C" void kernel_launch(void* const* d_in, const int* in_sizes, int n_in,
                              void* d_out, int out_size) {
    const float* feat = (const float*)d_in[0];
    const float* wt   = (const float*)d_in[1];
    float* out        = (float*)d_out;

    // smem = 3 x (A stage) + 3 x (B frag stage); all >= 67584 for epilogue scr
    constexpr int SM1 = 3 * (128 * 36 * 4) + 3 * 16384;   // 104448
    constexpr int SM3 = 3 * (44 * 104 * 4) + 3 * 16384;   // 104064
    constexpr int SM5 = 3 * (27 * 168 * 4) + 3 * 16384;   // 103584

    auto k1 = lin_k<1, 0,    50000>;
    auto k3 = lin_k<3, 256,  150000>;
    auto k5 = lin_k<5, 1024, 250000>;

    cudaFuncSetAttribute(k1, cudaFuncAttributeMaxDynamicSharedMemorySize, SM1);
    cudaFuncSetAttribute(k3, cudaFuncAttributeMaxDynamicSharedMemorySize, SM3);
    cudaFuncSetAttribute(k5, cudaFuncAttributeMaxDynamicSharedMemorySize, SM5);

    prep_w<<<192, 256>>>(wt);
    k1<<<391 * 2,  NTH, SM1>>>(feat, out);
    k3<<<1172 * 2, NTH, SM3>>>(feat, out);
    k5<<<1954 * 2, NTH, SM5>>>(feat, out);
}